// round 1
// baseline (speedup 1.0000x reference)
#include <cuda_runtime.h>
#include <cstddef>
#include <math.h>

#define BM 128
#define BN 128
#define BK 16

static const int Bsz = 8;
static const int Ssz = 2048;
static const int Hsz = 1024;
static const int Lsz = 4;
static const int Msz = Bsz * Ssz;   // 16384
static const int Nsz = 2 * Hsz;     // 2048
static const int Ksz = Hsz;         // 1024 (D == H)

// Scratch (device globals; no allocation allowed)
__device__ float g_GH[(size_t)Bsz * Ssz * 2 * Hsz];   // 128 MB
__device__ float g_buf0[(size_t)Bsz * Ssz * Hsz];     // 64 MB
__device__ float g_buf1[(size_t)Bsz * Ssz * Hsz];     // 64 MB

// C[M,N] = A[M,K] * Bw[N,K]^T + bias[N]
__global__ __launch_bounds__(256, 2) void gemm_kernel(
    const float* __restrict__ A, const float* __restrict__ Bw,
    const float* __restrict__ bias, float* __restrict__ C)
{
    __shared__ float As[BK][BM];
    __shared__ float Bs[BK][BN];

    const int tid = threadIdx.x;
    const int ty = tid >> 4;          // 0..15
    const int tx = tid & 15;          // 0..15
    const int m0 = blockIdx.y * BM;
    const int n0 = blockIdx.x * BN;

    const int lrow = tid >> 2;        // 0..63
    const int lcol = (tid & 3) << 2;  // 0,4,8,12

    const float* Ap = A + (size_t)(m0 + lrow) * Ksz + lcol;
    const float* Bp = Bw + (size_t)(n0 + lrow) * Ksz + lcol;

    float acc[8][8];
#pragma unroll
    for (int i = 0; i < 8; i++)
#pragma unroll
        for (int j = 0; j < 8; j++) acc[i][j] = 0.0f;

    for (int k0 = 0; k0 < Ksz; k0 += BK) {
        float4 a0 = *(const float4*)(Ap + k0);
        float4 a1 = *(const float4*)(Ap + (size_t)64 * Ksz + k0);
        float4 b0 = *(const float4*)(Bp + k0);
        float4 b1 = *(const float4*)(Bp + (size_t)64 * Ksz + k0);

        __syncthreads();
        As[lcol + 0][lrow] = a0.x; As[lcol + 1][lrow] = a0.y;
        As[lcol + 2][lrow] = a0.z; As[lcol + 3][lrow] = a0.w;
        As[lcol + 0][lrow + 64] = a1.x; As[lcol + 1][lrow + 64] = a1.y;
        As[lcol + 2][lrow + 64] = a1.z; As[lcol + 3][lrow + 64] = a1.w;
        Bs[lcol + 0][lrow] = b0.x; Bs[lcol + 1][lrow] = b0.y;
        Bs[lcol + 2][lrow] = b0.z; Bs[lcol + 3][lrow] = b0.w;
        Bs[lcol + 0][lrow + 64] = b1.x; Bs[lcol + 1][lrow + 64] = b1.y;
        Bs[lcol + 2][lrow + 64] = b1.z; Bs[lcol + 3][lrow + 64] = b1.w;
        __syncthreads();

#pragma unroll
        for (int kk = 0; kk < BK; kk++) {
            float4 af0 = *(const float4*)&As[kk][ty * 8];
            float4 af1 = *(const float4*)&As[kk][ty * 8 + 4];
            float4 bf0 = *(const float4*)&Bs[kk][tx * 8];
            float4 bf1 = *(const float4*)&Bs[kk][tx * 8 + 4];
            float av[8] = {af0.x, af0.y, af0.z, af0.w, af1.x, af1.y, af1.z, af1.w};
            float bv[8] = {bf0.x, bf0.y, bf0.z, bf0.w, bf1.x, bf1.y, bf1.z, bf1.w};
#pragma unroll
            for (int i = 0; i < 8; i++)
#pragma unroll
                for (int j = 0; j < 8; j++)
                    acc[i][j] = fmaf(av[i], bv[j], acc[i][j]);
        }
    }

#pragma unroll
    for (int j4 = 0; j4 < 8; j4 += 4) {
        float4 bb = *(const float4*)&bias[n0 + tx * 8 + j4];
#pragma unroll
        for (int i = 0; i < 8; i++) {
            float4 v;
            v.x = acc[i][j4 + 0] + bb.x;
            v.y = acc[i][j4 + 1] + bb.y;
            v.z = acc[i][j4 + 2] + bb.z;
            v.w = acc[i][j4 + 3] + bb.w;
            *(float4*)&C[(size_t)(m0 + ty * 8 + i) * Nsz + n0 + tx * 8 + j4] = v;
        }
    }
}

// Sequential scan over S per (b, h) channel, fused gate math + residual + finals.
// h_t = sigmoid(-gate)*h_{t-1} + sigmoid(gate)*g(hidden);  out = h_t + inp (residual)
__global__ __launch_bounds__(256) void scan_kernel(
    const float* __restrict__ GH, const float* __restrict__ inp,
    const float* __restrict__ h0, float* __restrict__ outp,
    float* __restrict__ finals)
{
    int idx = blockIdx.x * blockDim.x + threadIdx.x;   // 0 .. B*H-1
    int b = idx / Hsz;
    int n = idx % Hsz;

    const float* gh = GH + (size_t)b * Ssz * Nsz + n;
    const float* ip = inp + (size_t)b * Ssz * Hsz + n;
    float* op = outp + (size_t)b * Ssz * Hsz + n;

    // initial state = g(h_prev)
    float hp = h0[b * Hsz + n];
    float hstate;
    if (hp >= 0.0f) {
        hstate = hp + 0.5f;
    } else {
        float e = expf(hp);
        hstate = e / (1.0f + e);
    }

#pragma unroll 4
    for (int s = 0; s < Ssz; s++) {
        float gate = gh[(size_t)s * Nsz];
        float hid  = gh[(size_t)s * Nsz + Hsz];
        float xin  = ip[(size_t)s * Hsz];

        // z = sigmoid(gate), a = sigmoid(-gate), computed overflow-safe
        float e  = expf(-fabsf(gate));
        float sp = 1.0f / (1.0f + e);       // sigmoid(|gate|)
        float z  = (gate >= 0.0f) ? sp : e * sp;
        float a  = (gate >= 0.0f) ? e * sp : sp;

        // g(hidden) = hidden + 0.5 (hidden >= 0) else sigmoid(hidden)
        float gv;
        if (hid >= 0.0f) {
            gv = hid + 0.5f;
        } else {
            float eh = expf(hid);           // hid < 0: no overflow
            gv = eh / (1.0f + eh);
        }

        hstate = fmaf(a, hstate, z * gv);
        op[(size_t)s * Hsz] = hstate + xin;
    }
    finals[idx] = hstate;   // pre-residual last-step state
}

extern "C" void kernel_launch(void* const* d_in, const int* in_sizes, int n_in,
                              void* d_out, int out_size)
{
    const float* x  = (const float*)d_in[0];
    const float* h  = (const float*)d_in[1];
    const float* W0 = (const float*)d_in[2];
    const float* b0 = (const float*)d_in[3];
    const float* Wl = (const float*)d_in[4];
    const float* bl = (const float*)d_in[5];

    float* out_main = (float*)d_out;
    float* finals   = out_main + (size_t)Bsz * Ssz * Hsz;   // after (B,S,H) main output

    float *GH, *buf0, *buf1;
    cudaGetSymbolAddress((void**)&GH, g_GH);
    cudaGetSymbolAddress((void**)&buf0, g_buf0);
    cudaGetSymbolAddress((void**)&buf1, g_buf1);

    dim3 ggrid(Nsz / BN, Msz / BM);   // (16, 128)

    for (int l = 0; l < Lsz; l++) {
        const float* inp = (l == 0) ? x : (l == 1 ? buf0 : (l == 2 ? buf1 : buf0));
        const float* W   = (l == 0) ? W0 : Wl + (size_t)(l - 1) * Nsz * Hsz;
        const float* bi  = (l == 0) ? b0 : bl + (size_t)(l - 1) * Nsz;
        float* outp = (l == 3) ? out_main : ((l % 2 == 0) ? buf0 : buf1);

        gemm_kernel<<<ggrid, 256>>>(inp, W, bi, GH);
        scan_kernel<<<(Bsz * Hsz) / 256, 256>>>(
            GH, inp, h + (size_t)l * Bsz * Hsz, outp,
            finals + (size_t)l * Bsz * Hsz);
    }
}

// round 3
// speedup vs baseline: 1.5776x; 1.5776x over previous
#include <cuda_runtime.h>
#include <cuda_bf16.h>
#include <cstddef>
#include <cstdint>
#include <math.h>

// ---------------- problem sizes ----------------
#define Bsz 8
#define Ssz 2048
#define Hsz 1024
#define Lsz 4
#define Msz (Bsz * Ssz)   // 16384
#define Nsz (2 * Hsz)     // 2048
#define Ksz Hsz           // 1024

// ---------------- GEMM tile config ----------------
#define TM 128
#define TN 128
#define KC 64                 // bf16 per K-stage (128 B rows)
#define NKSTEP (Ksz / KC)     // 16
#define STAGE_BYTES 65536     // Ahi 16K | Alo 16K | Bhi 16K | Blo 16K
#define A_HI 0
#define A_LO 16384
#define B_HI 32768
#define B_LO 49152
#define SMEM_TOTAL (3 * STAGE_BYTES)

// ---------------- scratch ----------------
__device__ float g_GH[(size_t)Msz * Nsz];                      // 128 MB
__device__ float g_buf0[(size_t)Msz * Hsz];                    // 64 MB
__device__ float g_buf1[(size_t)Msz * Hsz];                    // 64 MB
__device__ __nv_bfloat16 g_Ahi[(size_t)Msz * Ksz];             // 32 MB
__device__ __nv_bfloat16 g_Alo[(size_t)Msz * Ksz];             // 32 MB
__device__ __nv_bfloat16 g_Bhi[(size_t)Lsz * Nsz * Ksz];       // 16 MB
__device__ __nv_bfloat16 g_Blo[(size_t)Lsz * Nsz * Ksz];       // 16 MB

// ---------------- PTX helpers (all plain-sm_103-safe) ----------------
__device__ __forceinline__ uint32_t smem_u32(const void* p) {
    uint32_t a;
    asm("{ .reg .u64 t; cvta.to.shared.u64 t, %1; cvt.u32.u64 %0, t; }" : "=r"(a) : "l"(p));
    return a;
}
#define CP_ASYNC16(dst, src) \
    asm volatile("cp.async.cg.shared.global [%0], [%1], 16;" :: "r"(dst), "l"(src) : "memory")
#define CP_COMMIT() asm volatile("cp.async.commit_group;" ::: "memory")
#define CP_WAIT2()  asm volatile("cp.async.wait_group 2;" ::: "memory")
#define CP_WAIT0()  asm volatile("cp.async.wait_group 0;" ::: "memory")

__device__ __forceinline__ void ldsm4(uint32_t* r, uint32_t addr) {
    asm volatile("ldmatrix.sync.aligned.m8n8.x4.shared.b16 {%0,%1,%2,%3}, [%4];"
        : "=r"(r[0]), "=r"(r[1]), "=r"(r[2]), "=r"(r[3]) : "r"(addr));
}
__device__ __forceinline__ void mma_bf16(float* d, const uint32_t* a, uint32_t b0, uint32_t b1) {
    asm volatile("mma.sync.aligned.m16n8k16.row.col.f32.bf16.bf16.f32 "
                 "{%0,%1,%2,%3}, {%4,%5,%6,%7}, {%8,%9}, {%0,%1,%2,%3};"
                 : "+f"(d[0]), "+f"(d[1]), "+f"(d[2]), "+f"(d[3])
                 : "r"(a[0]), "r"(a[1]), "r"(a[2]), "r"(a[3]), "r"(b0), "r"(b1));
}

// ---------------- stage loader: 128 rows x 128B each of Ahi/Alo/Bhi/Blo ----------------
__device__ __forceinline__ void load_stage(
    uint32_t sb, int m0, int n0, int k0,
    const __nv_bfloat16* __restrict__ Ahi, const __nv_bfloat16* __restrict__ Alo,
    const __nv_bfloat16* __restrict__ Bhi, const __nv_bfloat16* __restrict__ Blo)
{
    const int t = threadIdx.x;
    #pragma unroll
    for (int r = 0; r < 4; r++) {
        int c = t + r * 256;                 // 0..1023
        int row = c >> 3, ci = c & 7;
        uint32_t off = (uint32_t)(row << 7) + (((uint32_t)(ci << 4)) ^ ((uint32_t)(row & 7) << 4));
        size_t ga = (size_t)(m0 + row) * Ksz + k0 + ci * 8;
        size_t gb = (size_t)(n0 + row) * Ksz + k0 + ci * 8;
        CP_ASYNC16(sb + A_HI + off, Ahi + ga);
        CP_ASYNC16(sb + A_LO + off, Alo + ga);
        CP_ASYNC16(sb + B_HI + off, Bhi + gb);
        CP_ASYNC16(sb + B_LO + off, Blo + gb);
    }
    CP_COMMIT();
}

// ---------------- HMMA GEMM: C[M,N] = A*B^T + bias (3-term bf16 emulation) ----------------
__global__ __launch_bounds__(256, 1)
void gemm_mma_kernel(
    const __nv_bfloat16* __restrict__ Ahi, const __nv_bfloat16* __restrict__ Alo,
    const __nv_bfloat16* __restrict__ Bhi, const __nv_bfloat16* __restrict__ Blo,
    const float* __restrict__ bias, float* __restrict__ C)
{
    extern __shared__ __align__(1024) char smem[];
    const uint32_t sbase = smem_u32(smem);
    const int tid  = threadIdx.x;
    const int lane = tid & 31;
    const int w    = tid >> 5;
    const int m_warp = (w & 1) * 64;
    const int n_warp = (w >> 1) * 32;
    const int m0 = blockIdx.x * TM;
    const int n0 = blockIdx.y * TN;

    // per-lane invariant address pieces
    const uint32_t xv = (uint32_t)(lane & 7) << 4;
    const uint32_t a_rowbase = (uint32_t)(m_warp + (lane & 15)) << 7;
    const uint32_t a_khalf   = (uint32_t)(lane >> 4) << 4;
    const uint32_t b_rowbase = (uint32_t)(n_warp + ((lane >> 4) << 3) + (lane & 7)) << 7;
    const uint32_t b_khalf   = (uint32_t)((lane >> 3) & 1) << 4;

    float acc[4][4][4];
    #pragma unroll
    for (int i = 0; i < 4; i++)
        #pragma unroll
        for (int j = 0; j < 4; j++)
            #pragma unroll
            for (int q = 0; q < 4; q++) acc[i][j][q] = 0.0f;

    // prologue: 3 stages in flight
    load_stage(sbase,                   m0, n0, 0,      Ahi, Alo, Bhi, Blo);
    load_stage(sbase + STAGE_BYTES,     m0, n0, KC,     Ahi, Alo, Bhi, Blo);
    load_stage(sbase + 2 * STAGE_BYTES, m0, n0, 2 * KC, Ahi, Alo, Bhi, Blo);

    #pragma unroll 1
    for (int s = 0; s < NKSTEP; s++) {
        if (s < NKSTEP - 2) { CP_WAIT2(); } else { CP_WAIT0(); }
        __syncthreads();

        const uint32_t sb = sbase + (uint32_t)(s % 3) * STAGE_BYTES;

        #pragma unroll
        for (int ks = 0; ks < 4; ks++) {
            const uint32_t kb = (uint32_t)(ks * 32);
            uint32_t ah[4][4], al[4][4], bh[2][4], bl[2][4];
            #pragma unroll
            for (int i = 0; i < 4; i++) {
                uint32_t aoff = a_rowbase + ((uint32_t)(i * 16) << 7) + ((kb + a_khalf) ^ xv);
                ldsm4(ah[i], sb + A_HI + aoff);
                ldsm4(al[i], sb + A_LO + aoff);
            }
            #pragma unroll
            for (int j = 0; j < 2; j++) {
                uint32_t boff = b_rowbase + ((uint32_t)(j * 16) << 7) + ((kb + b_khalf) ^ xv);
                ldsm4(bh[j], sb + B_HI + boff);
                ldsm4(bl[j], sb + B_LO + boff);
            }
            #pragma unroll
            for (int i = 0; i < 4; i++) {
                #pragma unroll
                for (int jt = 0; jt < 4; jt++) {
                    const int jp = jt >> 1, jo = (jt & 1) * 2;
                    mma_bf16(acc[i][jt], ah[i], bh[jp][jo], bh[jp][jo + 1]);
                    mma_bf16(acc[i][jt], ah[i], bl[jp][jo], bl[jp][jo + 1]);
                    mma_bf16(acc[i][jt], al[i], bh[jp][jo], bh[jp][jo + 1]);
                }
            }
        }

        __syncthreads();  // all warps done reading stage s before refilling its buffer
        if (s + 3 < NKSTEP)
            load_stage(sb, m0, n0, (s + 3) * KC, Ahi, Alo, Bhi, Blo);
    }

    // epilogue: C += bias, fp32 stores
    const int trow = lane >> 2;
    const int tcol = (lane & 3) * 2;
    #pragma unroll
    for (int i = 0; i < 4; i++) {
        #pragma unroll
        for (int jt = 0; jt < 4; jt++) {
            int row = m0 + m_warp + i * 16 + trow;
            int col = n0 + n_warp + jt * 8 + tcol;
            float2 bv = *(const float2*)&bias[col];
            float2 v0 = { acc[i][jt][0] + bv.x, acc[i][jt][1] + bv.y };
            float2 v1 = { acc[i][jt][2] + bv.x, acc[i][jt][3] + bv.y };
            *(float2*)&C[(size_t)row * Nsz + col] = v0;
            *(float2*)&C[(size_t)(row + 8) * Nsz + col] = v1;
        }
    }
}

// ---------------- hi/lo split conversions ----------------
__device__ __forceinline__ void split1(float v, __nv_bfloat16& h, __nv_bfloat16& l) {
    h = __float2bfloat16(v);
    l = __float2bfloat16(v - __bfloat162float(h));
}

__global__ __launch_bounds__(256) void conv_x_kernel(
    const float* __restrict__ src, __nv_bfloat16* __restrict__ hi, __nv_bfloat16* __restrict__ lo)
{
    size_t i = (size_t)blockIdx.x * 256 + threadIdx.x;   // float4 index
    float4 v = ((const float4*)src)[i];
    __nv_bfloat16 h0, h1, h2, h3, l0, l1, l2, l3;
    split1(v.x, h0, l0); split1(v.y, h1, l1); split1(v.z, h2, l2); split1(v.w, h3, l3);
    ((__nv_bfloat162*)hi)[2 * i + 0] = __nv_bfloat162(h0, h1);
    ((__nv_bfloat162*)hi)[2 * i + 1] = __nv_bfloat162(h2, h3);
    ((__nv_bfloat162*)lo)[2 * i + 0] = __nv_bfloat162(l0, l1);
    ((__nv_bfloat162*)lo)[2 * i + 1] = __nv_bfloat162(l2, l3);
}

__global__ __launch_bounds__(256) void conv_w_kernel(
    const float* __restrict__ W0, const float* __restrict__ Wl,
    __nv_bfloat16* __restrict__ hi, __nv_bfloat16* __restrict__ lo)
{
    size_t i = (size_t)blockIdx.x * 256 + threadIdx.x;   // float4 index over 4 layers
    size_t layer = i >> 19;                              // 2M elems / 4 per layer
    const float* src = (layer == 0) ? W0 : (Wl + ((layer - 1) << 21));
    size_t li = i & ((1 << 19) - 1);
    float4 v = ((const float4*)src)[li];
    __nv_bfloat16 h0, h1, h2, h3, l0, l1, l2, l3;
    split1(v.x, h0, l0); split1(v.y, h1, l1); split1(v.z, h2, l2); split1(v.w, h3, l3);
    ((__nv_bfloat162*)hi)[2 * i + 0] = __nv_bfloat162(h0, h1);
    ((__nv_bfloat162*)hi)[2 * i + 1] = __nv_bfloat162(h2, h3);
    ((__nv_bfloat162*)lo)[2 * i + 0] = __nv_bfloat162(l0, l1);
    ((__nv_bfloat162*)lo)[2 * i + 1] = __nv_bfloat162(l2, l3);
}

// ---------------- scan (fused gates + residual + finals + next-layer hi/lo) ----------------
__global__ __launch_bounds__(256) void scan_kernel(
    const float* __restrict__ GH, const float* __restrict__ inp,
    const float* __restrict__ h0, float* __restrict__ outp,
    float* __restrict__ finals,
    __nv_bfloat16* __restrict__ nAhi, __nv_bfloat16* __restrict__ nAlo)
{
    int idx = blockIdx.x * blockDim.x + threadIdx.x;   // 0 .. B*H-1
    int b = idx / Hsz;
    int n = idx % Hsz;

    const float* gh = GH + (size_t)b * Ssz * Nsz + n;
    const float* ip = inp + (size_t)b * Ssz * Hsz + n;
    float* op = outp + (size_t)b * Ssz * Hsz + n;
    __nv_bfloat16* ah = nAhi ? nAhi + (size_t)b * Ssz * Hsz + n : nullptr;
    __nv_bfloat16* al = nAlo ? nAlo + (size_t)b * Ssz * Hsz + n : nullptr;

    float hp = h0[b * Hsz + n];
    float hstate;
    if (hp >= 0.0f) hstate = hp + 0.5f;
    else { float e = expf(hp); hstate = e / (1.0f + e); }

    #pragma unroll 4
    for (int s = 0; s < Ssz; s++) {
        float gate = gh[(size_t)s * Nsz];
        float hid  = gh[(size_t)s * Nsz + Hsz];
        float xin  = ip[(size_t)s * Hsz];

        float e  = expf(-fabsf(gate));
        float sp = 1.0f / (1.0f + e);
        float z  = (gate >= 0.0f) ? sp : e * sp;
        float a  = (gate >= 0.0f) ? e * sp : sp;

        float gv;
        if (hid >= 0.0f) gv = hid + 0.5f;
        else { float eh = expf(hid); gv = eh / (1.0f + eh); }

        hstate = fmaf(a, hstate, z * gv);
        float o = hstate + xin;
        op[(size_t)s * Hsz] = o;
        if (ah) {
            __nv_bfloat16 h = __float2bfloat16(o);
            __nv_bfloat16 l = __float2bfloat16(o - __bfloat162float(h));
            ah[(size_t)s * Hsz] = h;
            al[(size_t)s * Hsz] = l;
        }
    }
    finals[idx] = hstate;
}

// ---------------- launch ----------------
extern "C" void kernel_launch(void* const* d_in, const int* in_sizes, int n_in,
                              void* d_out, int out_size)
{
    const float* x  = (const float*)d_in[0];
    const float* h  = (const float*)d_in[1];
    const float* W0 = (const float*)d_in[2];
    const float* b0 = (const float*)d_in[3];
    const float* Wl = (const float*)d_in[4];
    const float* bl = (const float*)d_in[5];

    float* out_main = (float*)d_out;
    float* finals   = out_main + (size_t)Msz * Hsz;

    float *GH, *buf0, *buf1;
    __nv_bfloat16 *Ahi, *Alo, *Bhi, *Blo;
    cudaGetSymbolAddress((void**)&GH, g_GH);
    cudaGetSymbolAddress((void**)&buf0, g_buf0);
    cudaGetSymbolAddress((void**)&buf1, g_buf1);
    cudaGetSymbolAddress((void**)&Ahi, g_Ahi);
    cudaGetSymbolAddress((void**)&Alo, g_Alo);
    cudaGetSymbolAddress((void**)&Bhi, g_Bhi);
    cudaGetSymbolAddress((void**)&Blo, g_Blo);

    cudaFuncSetAttribute(gemm_mma_kernel, cudaFuncAttributeMaxDynamicSharedMemorySize, SMEM_TOTAL);

    conv_w_kernel<<<(4 * 2097152 / 4) / 256, 256>>>(W0, Wl, Bhi, Blo);
    conv_x_kernel<<<((size_t)Msz * Ksz / 4) / 256, 256>>>(x, Ahi, Alo);

    dim3 ggrid(Msz / TM, Nsz / TN);   // (128, 16)

    for (int l = 0; l < Lsz; l++) {
        const float* inp = (l == 0) ? x : (l == 1 ? buf0 : (l == 2 ? buf1 : buf0));
        const float* bi  = (l == 0) ? b0 : bl + (size_t)(l - 1) * Nsz;
        float* outp = (l == 3) ? out_main : ((l % 2 == 0) ? buf0 : buf1);
        __nv_bfloat16* nAhi = (l < 3) ? Ahi : nullptr;
        __nv_bfloat16* nAlo = (l < 3) ? Alo : nullptr;

        gemm_mma_kernel<<<ggrid, 256, SMEM_TOTAL>>>(
            Ahi, Alo, Bhi + (size_t)l * Nsz * Ksz, Blo + (size_t)l * Nsz * Ksz, bi, GH);
        scan_kernel<<<(Bsz * Hsz) / 256, 256>>>(
            GH, inp, h + (size_t)l * Bsz * Hsz, outp,
            finals + (size_t)l * Bsz * Hsz, nAhi, nAlo);
    }
}

// round 4
// speedup vs baseline: 1.8912x; 1.1988x over previous
#include <cuda_runtime.h>
#include <cuda_fp16.h>
#include <cstddef>
#include <cstdint>
#include <math.h>

// ---------------- problem sizes ----------------
#define Bsz 8
#define Ssz 2048
#define Hsz 1024
#define Lsz 4
#define Msz (Bsz * Ssz)   // 16384
#define Nsz (2 * Hsz)     // 2048
#define Ksz Hsz           // 1024

// ---------------- GEMM tile config ----------------
#define TM 128
#define TN 128
#define KC 64                 // fp16 per K-stage (128 B rows)
#define NKSTEP (Ksz / KC)     // 16
#define STAGE_BYTES 32768     // A 16K | B 16K
#define A_OFF 0
#define B_OFF 16384
#define SMEM_TOTAL (3 * STAGE_BYTES)   // 96 KB -> 2 CTAs/SM

// ---------------- scratch ----------------
__device__ float g_GH[(size_t)Msz * Nsz];                 // 128 MB
__device__ float g_buf0[(size_t)Msz * Hsz];               // 64 MB
__device__ float g_buf1[(size_t)Msz * Hsz];               // 64 MB
__device__ __half g_A16[(size_t)Msz * Ksz];               // 32 MB
__device__ __half g_B16[(size_t)Lsz * Nsz * Ksz];         // 16 MB

// ---------------- PTX helpers (plain-sm_103-safe) ----------------
__device__ __forceinline__ uint32_t smem_u32(const void* p) {
    uint32_t a;
    asm("{ .reg .u64 t; cvta.to.shared.u64 t, %1; cvt.u32.u64 %0, t; }" : "=r"(a) : "l"(p));
    return a;
}
#define CP_ASYNC16(dst, src) \
    asm volatile("cp.async.cg.shared.global [%0], [%1], 16;" :: "r"(dst), "l"(src) : "memory")
#define CP_COMMIT() asm volatile("cp.async.commit_group;" ::: "memory")
#define CP_WAIT2()  asm volatile("cp.async.wait_group 2;" ::: "memory")
#define CP_WAIT0()  asm volatile("cp.async.wait_group 0;" ::: "memory")

__device__ __forceinline__ void ldsm4(uint32_t* r, uint32_t addr) {
    asm volatile("ldmatrix.sync.aligned.m8n8.x4.shared.b16 {%0,%1,%2,%3}, [%4];"
        : "=r"(r[0]), "=r"(r[1]), "=r"(r[2]), "=r"(r[3]) : "r"(addr));
}
__device__ __forceinline__ void mma_fp16(float* d, const uint32_t* a, uint32_t b0, uint32_t b1) {
    asm volatile("mma.sync.aligned.m16n8k16.row.col.f32.f16.f16.f32 "
                 "{%0,%1,%2,%3}, {%4,%5,%6,%7}, {%8,%9}, {%0,%1,%2,%3};"
                 : "+f"(d[0]), "+f"(d[1]), "+f"(d[2]), "+f"(d[3])
                 : "r"(a[0]), "r"(a[1]), "r"(a[2]), "r"(a[3]), "r"(b0), "r"(b1));
}

// ---------------- stage loader: 128 rows x 128B for A and B ----------------
__device__ __forceinline__ void load_stage(
    uint32_t sb, int m0, int n0, int k0,
    const __half* __restrict__ A16, const __half* __restrict__ B16)
{
    const int t = threadIdx.x;
    #pragma unroll
    for (int r = 0; r < 4; r++) {
        int c = t + r * 256;                 // 0..1023
        int row = c >> 3, ci = c & 7;
        uint32_t off = (uint32_t)(row << 7) + (((uint32_t)(ci << 4)) ^ ((uint32_t)(row & 7) << 4));
        size_t ga = (size_t)(m0 + row) * Ksz + k0 + ci * 8;
        size_t gb = (size_t)(n0 + row) * Ksz + k0 + ci * 8;
        CP_ASYNC16(sb + A_OFF + off, A16 + ga);
        CP_ASYNC16(sb + B_OFF + off, B16 + gb);
    }
    CP_COMMIT();
}

// ---------------- HMMA GEMM: C[M,N] = A*B^T + bias ----------------
__global__ __launch_bounds__(256, 2)
void gemm_mma_kernel(
    const __half* __restrict__ A16, const __half* __restrict__ B16,
    const float* __restrict__ bias, float* __restrict__ C)
{
    extern __shared__ __align__(1024) char smem[];
    const uint32_t sbase = smem_u32(smem);
    const int tid  = threadIdx.x;
    const int lane = tid & 31;
    const int w    = tid >> 5;
    const int m_warp = (w & 1) * 64;
    const int n_warp = (w >> 1) * 32;
    const int m0 = blockIdx.x * TM;
    const int n0 = blockIdx.y * TN;

    const uint32_t xv = (uint32_t)(lane & 7) << 4;
    const uint32_t a_rowbase = (uint32_t)(m_warp + (lane & 15)) << 7;
    const uint32_t a_khalf   = (uint32_t)(lane >> 4) << 4;
    const uint32_t b_rowbase = (uint32_t)(n_warp + ((lane >> 4) << 3) + (lane & 7)) << 7;
    const uint32_t b_khalf   = (uint32_t)((lane >> 3) & 1) << 4;

    float acc[4][4][4];
    #pragma unroll
    for (int i = 0; i < 4; i++)
        #pragma unroll
        for (int j = 0; j < 4; j++)
            #pragma unroll
            for (int q = 0; q < 4; q++) acc[i][j][q] = 0.0f;

    load_stage(sbase,                   m0, n0, 0,      A16, B16);
    load_stage(sbase + STAGE_BYTES,     m0, n0, KC,     A16, B16);
    load_stage(sbase + 2 * STAGE_BYTES, m0, n0, 2 * KC, A16, B16);

    #pragma unroll 1
    for (int s = 0; s < NKSTEP; s++) {
        if (s < NKSTEP - 2) { CP_WAIT2(); } else { CP_WAIT0(); }
        __syncthreads();

        const uint32_t sb = sbase + (uint32_t)(s % 3) * STAGE_BYTES;

        #pragma unroll
        for (int ks = 0; ks < 4; ks++) {
            const uint32_t kb = (uint32_t)(ks * 32);
            uint32_t ah[4][4], bh[2][4];
            #pragma unroll
            for (int i = 0; i < 4; i++) {
                uint32_t aoff = a_rowbase + ((uint32_t)(i * 16) << 7) + ((kb + a_khalf) ^ xv);
                ldsm4(ah[i], sb + A_OFF + aoff);
            }
            #pragma unroll
            for (int j = 0; j < 2; j++) {
                uint32_t boff = b_rowbase + ((uint32_t)(j * 16) << 7) + ((kb + b_khalf) ^ xv);
                ldsm4(bh[j], sb + B_OFF + boff);
            }
            #pragma unroll
            for (int i = 0; i < 4; i++) {
                #pragma unroll
                for (int jt = 0; jt < 4; jt++) {
                    const int jp = jt >> 1, jo = (jt & 1) * 2;
                    mma_fp16(acc[i][jt], ah[i], bh[jp][jo], bh[jp][jo + 1]);
                }
            }
        }

        __syncthreads();  // all warps done reading stage s before refilling its buffer
        if (s + 3 < NKSTEP)
            load_stage(sb, m0, n0, (s + 3) * KC, A16, B16);
    }

    // epilogue: C = acc + bias
    const int trow = lane >> 2;
    const int tcol = (lane & 3) * 2;
    #pragma unroll
    for (int i = 0; i < 4; i++) {
        #pragma unroll
        for (int jt = 0; jt < 4; jt++) {
            int row = m0 + m_warp + i * 16 + trow;
            int col = n0 + n_warp + jt * 8 + tcol;
            float2 bv = *(const float2*)&bias[col];
            float2 v0 = { acc[i][jt][0] + bv.x, acc[i][jt][1] + bv.y };
            float2 v1 = { acc[i][jt][2] + bv.x, acc[i][jt][3] + bv.y };
            *(float2*)&C[(size_t)row * Nsz + col] = v0;
            *(float2*)&C[(size_t)(row + 8) * Nsz + col] = v1;
        }
    }
}

// ---------------- fp32 -> fp16 conversions ----------------
__global__ __launch_bounds__(256) void conv_x_kernel(
    const float* __restrict__ src, __half* __restrict__ dst)
{
    size_t i = (size_t)blockIdx.x * 256 + threadIdx.x;   // float4 index
    float4 v = ((const float4*)src)[i];
    __half2 h0 = __floats2half2_rn(v.x, v.y);
    __half2 h1 = __floats2half2_rn(v.z, v.w);
    ((__half2*)dst)[2 * i + 0] = h0;
    ((__half2*)dst)[2 * i + 1] = h1;
}

__global__ __launch_bounds__(256) void conv_w_kernel(
    const float* __restrict__ W0, const float* __restrict__ Wl, __half* __restrict__ dst)
{
    size_t i = (size_t)blockIdx.x * 256 + threadIdx.x;   // float4 index over 4 layers
    size_t layer = i >> 19;                              // 2M elems / 4 per layer
    const float* src = (layer == 0) ? W0 : (Wl + ((layer - 1) << 21));
    size_t li = i & ((1 << 19) - 1);
    float4 v = ((const float4*)src)[li];
    ((__half2*)dst)[2 * i + 0] = __floats2half2_rn(v.x, v.y);
    ((__half2*)dst)[2 * i + 1] = __floats2half2_rn(v.z, v.w);
}

// ---------------- scan (fused gates + residual + finals + next-layer fp16 export) ----------------
__global__ __launch_bounds__(256) void scan_kernel(
    const float* __restrict__ GH, const float* __restrict__ inp,
    const float* __restrict__ h0, float* __restrict__ outp,
    float* __restrict__ finals, __half* __restrict__ nA)
{
    int idx = blockIdx.x * blockDim.x + threadIdx.x;   // 0 .. B*H-1
    int b = idx / Hsz;
    int n = idx % Hsz;

    const float* gh = GH + (size_t)b * Ssz * Nsz + n;
    const float* ip = inp + (size_t)b * Ssz * Hsz + n;
    float* op = outp + (size_t)b * Ssz * Hsz + n;
    __half* ap = nA ? nA + (size_t)b * Ssz * Hsz + n : nullptr;

    float hp = h0[b * Hsz + n];
    float hstate;
    if (hp >= 0.0f) hstate = hp + 0.5f;
    else { float e = expf(hp); hstate = e / (1.0f + e); }

    #pragma unroll 4
    for (int s = 0; s < Ssz; s++) {
        float gate = gh[(size_t)s * Nsz];
        float hid  = gh[(size_t)s * Nsz + Hsz];
        float xin  = ip[(size_t)s * Hsz];

        float e  = expf(-fabsf(gate));
        float sp = 1.0f / (1.0f + e);
        float z  = (gate >= 0.0f) ? sp : e * sp;
        float a  = (gate >= 0.0f) ? e * sp : sp;

        float gv;
        if (hid >= 0.0f) gv = hid + 0.5f;
        else { float eh = expf(hid); gv = eh / (1.0f + eh); }

        hstate = fmaf(a, hstate, z * gv);
        float o = hstate + xin;
        op[(size_t)s * Hsz] = o;
        if (ap) ap[(size_t)s * Hsz] = __float2half(o);
    }
    finals[idx] = hstate;
}

// ---------------- launch ----------------
extern "C" void kernel_launch(void* const* d_in, const int* in_sizes, int n_in,
                              void* d_out, int out_size)
{
    const float* x  = (const float*)d_in[0];
    const float* h  = (const float*)d_in[1];
    const float* W0 = (const float*)d_in[2];
    const float* b0 = (const float*)d_in[3];
    const float* Wl = (const float*)d_in[4];
    const float* bl = (const float*)d_in[5];

    float* out_main = (float*)d_out;
    float* finals   = out_main + (size_t)Msz * Hsz;

    float *GH, *buf0, *buf1;
    __half *A16, *B16;
    cudaGetSymbolAddress((void**)&GH, g_GH);
    cudaGetSymbolAddress((void**)&buf0, g_buf0);
    cudaGetSymbolAddress((void**)&buf1, g_buf1);
    cudaGetSymbolAddress((void**)&A16, g_A16);
    cudaGetSymbolAddress((void**)&B16, g_B16);

    cudaFuncSetAttribute(gemm_mma_kernel, cudaFuncAttributeMaxDynamicSharedMemorySize, SMEM_TOTAL);

    conv_w_kernel<<<(4 * 2097152 / 4) / 256, 256>>>(W0, Wl, B16);
    conv_x_kernel<<<((size_t)Msz * Ksz / 4) / 256, 256>>>(x, A16);

    dim3 ggrid(Msz / TM, Nsz / TN);   // (128, 16)

    for (int l = 0; l < Lsz; l++) {
        const float* inp = (l == 0) ? x : (l == 1 ? buf0 : (l == 2 ? buf1 : buf0));
        const float* bi  = (l == 0) ? b0 : bl + (size_t)(l - 1) * Nsz;
        float* outp = (l == 3) ? out_main : ((l % 2 == 0) ? buf0 : buf1);
        __half* nA = (l < 3) ? A16 : nullptr;

        gemm_mma_kernel<<<ggrid, 256, SMEM_TOTAL>>>(
            A16, B16 + (size_t)l * Nsz * Ksz, bi, GH);
        scan_kernel<<<(Bsz * Hsz) / 256, 256>>>(
            GH, inp, h + (size_t)l * Bsz * Hsz, outp,
            finals + (size_t)l * Bsz * Hsz, nA);
    }
}

// round 5
// speedup vs baseline: 7.8421x; 4.1466x over previous
#include <cuda_runtime.h>
#include <cuda_fp16.h>
#include <cstddef>
#include <cstdint>
#include <math.h>

// ---------------- problem sizes ----------------
#define Bsz 8
#define Ssz 2048
#define Hsz 1024
#define Lsz 4
#define Msz (Bsz * Ssz)   // 16384
#define Nsz (2 * Hsz)     // 2048
#define Ksz Hsz           // 1024

// ---------------- scan chunking ----------------
#define NC 16             // chunks per sequence
#define CL (Ssz / NC)     // 128 steps per chunk
#define NCH (Bsz * Hsz)   // 8192 channels
#define NTH (NCH * NC)    // 131072 chunk-threads

// ---------------- GEMM tile config ----------------
#define TM 128
#define TN 128
#define KC 64                 // fp16 per K-stage (128 B rows)
#define NKSTEP (Ksz / KC)     // 16
#define STAGE_BYTES 32768     // A 16K | B 16K
#define A_OFF 0
#define B_OFF 16384
#define SMEM_TOTAL (3 * STAGE_BYTES)   // 96 KB -> 2 CTAs/SM

// ---------------- scratch ----------------
__device__ float g_GH[(size_t)Msz * Nsz];                 // 128 MB
__device__ float g_buf0[(size_t)Msz * Hsz];               // 64 MB
__device__ float g_buf1[(size_t)Msz * Hsz];               // 64 MB
__device__ __half g_A16[(size_t)Msz * Ksz];               // 32 MB
__device__ __half g_B16[(size_t)Lsz * Nsz * Ksz];         // 16 MB
__device__ float g_cA[NTH];                               // chunk a-products
__device__ float g_cH[NTH];                               // chunk partial states
__device__ float g_cS[NTH];                               // chunk start states

// ---------------- PTX helpers (plain-sm_103-safe) ----------------
__device__ __forceinline__ uint32_t smem_u32(const void* p) {
    uint32_t a;
    asm("{ .reg .u64 t; cvta.to.shared.u64 t, %1; cvt.u32.u64 %0, t; }" : "=r"(a) : "l"(p));
    return a;
}
#define CP_ASYNC16(dst, src) \
    asm volatile("cp.async.cg.shared.global [%0], [%1], 16;" :: "r"(dst), "l"(src) : "memory")
#define CP_COMMIT() asm volatile("cp.async.commit_group;" ::: "memory")
#define CP_WAIT2()  asm volatile("cp.async.wait_group 2;" ::: "memory")
#define CP_WAIT0()  asm volatile("cp.async.wait_group 0;" ::: "memory")

__device__ __forceinline__ void ldsm4(uint32_t* r, uint32_t addr) {
    asm volatile("ldmatrix.sync.aligned.m8n8.x4.shared.b16 {%0,%1,%2,%3}, [%4];"
        : "=r"(r[0]), "=r"(r[1]), "=r"(r[2]), "=r"(r[3]) : "r"(addr));
}
__device__ __forceinline__ void mma_fp16(float* d, const uint32_t* a, uint32_t b0, uint32_t b1) {
    asm volatile("mma.sync.aligned.m16n8k16.row.col.f32.f16.f16.f32 "
                 "{%0,%1,%2,%3}, {%4,%5,%6,%7}, {%8,%9}, {%0,%1,%2,%3};"
                 : "+f"(d[0]), "+f"(d[1]), "+f"(d[2]), "+f"(d[3])
                 : "r"(a[0]), "r"(a[1]), "r"(a[2]), "r"(a[3]), "r"(b0), "r"(b1));
}

// ---------------- stage loader ----------------
__device__ __forceinline__ void load_stage(
    uint32_t sb, int m0, int n0, int k0,
    const __half* __restrict__ A16, const __half* __restrict__ B16)
{
    const int t = threadIdx.x;
    #pragma unroll
    for (int r = 0; r < 4; r++) {
        int c = t + r * 256;                 // 0..1023
        int row = c >> 3, ci = c & 7;
        uint32_t off = (uint32_t)(row << 7) + (((uint32_t)(ci << 4)) ^ ((uint32_t)(row & 7) << 4));
        size_t ga = (size_t)(m0 + row) * Ksz + k0 + ci * 8;
        size_t gb = (size_t)(n0 + row) * Ksz + k0 + ci * 8;
        CP_ASYNC16(sb + A_OFF + off, A16 + ga);
        CP_ASYNC16(sb + B_OFF + off, B16 + gb);
    }
    CP_COMMIT();
}

// ---------------- HMMA GEMM: C[M,N] = A*B^T + bias ----------------
__global__ __launch_bounds__(256, 2)
void gemm_mma_kernel(
    const __half* __restrict__ A16, const __half* __restrict__ B16,
    const float* __restrict__ bias, float* __restrict__ C)
{
    extern __shared__ __align__(1024) char smem[];
    const uint32_t sbase = smem_u32(smem);
    const int tid  = threadIdx.x;
    const int lane = tid & 31;
    const int w    = tid >> 5;
    const int m_warp = (w & 1) * 64;
    const int n_warp = (w >> 1) * 32;
    const int m0 = blockIdx.x * TM;
    const int n0 = blockIdx.y * TN;

    const uint32_t xv = (uint32_t)(lane & 7) << 4;
    const uint32_t a_rowbase = (uint32_t)(m_warp + (lane & 15)) << 7;
    const uint32_t a_khalf   = (uint32_t)(lane >> 4) << 4;
    const uint32_t b_rowbase = (uint32_t)(n_warp + ((lane >> 4) << 3) + (lane & 7)) << 7;
    const uint32_t b_khalf   = (uint32_t)((lane >> 3) & 1) << 4;

    float acc[4][4][4];
    #pragma unroll
    for (int i = 0; i < 4; i++)
        #pragma unroll
        for (int j = 0; j < 4; j++)
            #pragma unroll
            for (int q = 0; q < 4; q++) acc[i][j][q] = 0.0f;

    load_stage(sbase,                   m0, n0, 0,      A16, B16);
    load_stage(sbase + STAGE_BYTES,     m0, n0, KC,     A16, B16);
    load_stage(sbase + 2 * STAGE_BYTES, m0, n0, 2 * KC, A16, B16);

    #pragma unroll 1
    for (int s = 0; s < NKSTEP; s++) {
        if (s < NKSTEP - 2) { CP_WAIT2(); } else { CP_WAIT0(); }
        __syncthreads();

        const uint32_t sb = sbase + (uint32_t)(s % 3) * STAGE_BYTES;

        #pragma unroll
        for (int ks = 0; ks < 4; ks++) {
            const uint32_t kb = (uint32_t)(ks * 32);
            uint32_t ah[4][4], bh[2][4];
            #pragma unroll
            for (int i = 0; i < 4; i++) {
                uint32_t aoff = a_rowbase + ((uint32_t)(i * 16) << 7) + ((kb + a_khalf) ^ xv);
                ldsm4(ah[i], sb + A_OFF + aoff);
            }
            #pragma unroll
            for (int j = 0; j < 2; j++) {
                uint32_t boff = b_rowbase + ((uint32_t)(j * 16) << 7) + ((kb + b_khalf) ^ xv);
                ldsm4(bh[j], sb + B_OFF + boff);
            }
            #pragma unroll
            for (int i = 0; i < 4; i++) {
                #pragma unroll
                for (int jt = 0; jt < 4; jt++) {
                    const int jp = jt >> 1, jo = (jt & 1) * 2;
                    mma_fp16(acc[i][jt], ah[i], bh[jp][jo], bh[jp][jo + 1]);
                }
            }
        }

        __syncthreads();
        if (s + 3 < NKSTEP)
            load_stage(sb, m0, n0, (s + 3) * KC, A16, B16);
    }

    const int trow = lane >> 2;
    const int tcol = (lane & 3) * 2;
    #pragma unroll
    for (int i = 0; i < 4; i++) {
        #pragma unroll
        for (int jt = 0; jt < 4; jt++) {
            int row = m0 + m_warp + i * 16 + trow;
            int col = n0 + n_warp + jt * 8 + tcol;
            float2 bv = *(const float2*)&bias[col];
            float2 v0 = { acc[i][jt][0] + bv.x, acc[i][jt][1] + bv.y };
            float2 v1 = { acc[i][jt][2] + bv.x, acc[i][jt][3] + bv.y };
            *(float2*)&C[(size_t)row * Nsz + col] = v0;
            *(float2*)&C[(size_t)(row + 8) * Nsz + col] = v1;
        }
    }
}

// ---------------- fp32 -> fp16 conversions ----------------
__global__ __launch_bounds__(256) void conv_x_kernel(
    const float* __restrict__ src, __half* __restrict__ dst)
{
    size_t i = (size_t)blockIdx.x * 256 + threadIdx.x;
    float4 v = ((const float4*)src)[i];
    ((__half2*)dst)[2 * i + 0] = __floats2half2_rn(v.x, v.y);
    ((__half2*)dst)[2 * i + 1] = __floats2half2_rn(v.z, v.w);
}

__global__ __launch_bounds__(256) void conv_w_kernel(
    const float* __restrict__ W0, const float* __restrict__ Wl, __half* __restrict__ dst)
{
    size_t i = (size_t)blockIdx.x * 256 + threadIdx.x;
    size_t layer = i >> 19;
    const float* src = (layer == 0) ? W0 : (Wl + ((layer - 1) << 21));
    size_t li = i & ((1 << 19) - 1);
    float4 v = ((const float4*)src)[li];
    ((__half2*)dst)[2 * i + 0] = __floats2half2_rn(v.x, v.y);
    ((__half2*)dst)[2 * i + 1] = __floats2half2_rn(v.z, v.w);
}

// ---------------- gate math ----------------
__device__ __forceinline__ void gates(float gate, float hid, float& a, float& zg) {
    float e  = expf(-fabsf(gate));
    float sp = 1.0f / (1.0f + e);
    float z, gv;
    if (gate >= 0.0f) { z = sp; a = e * sp; }
    else              { z = e * sp; a = sp; }
    if (hid >= 0.0f) gv = hid + 0.5f;
    else { float eh = expf(hid); gv = eh / (1.0f + eh); }
    zg = z * gv;
}

// ---------------- S1: per-chunk (a-product, partial state) ----------------
__global__ __launch_bounds__(256) void scan1_kernel(
    const float* __restrict__ GH, float* __restrict__ cA, float* __restrict__ cH)
{
    int idx = blockIdx.x * 256 + threadIdx.x;       // ((b*NC + c)*Hsz) + n
    int n = idx & (Hsz - 1);
    int bc = idx >> 10;
    int c = bc & (NC - 1);
    int b = bc >> 4;

    const float* gh = GH + ((size_t)b * Ssz + (size_t)c * CL) * Nsz + n;

    float aprod = 1.0f, hpart = 0.0f;
    #pragma unroll 4
    for (int i = 0; i < CL; i++) {
        float gate = gh[(size_t)i * Nsz];
        float hid  = gh[(size_t)i * Nsz + Hsz];
        float a, zg;
        gates(gate, hid, a, zg);
        hpart = fmaf(a, hpart, zg);
        aprod *= a;
    }
    cA[idx] = aprod;
    cH[idx] = hpart;
}

// ---------------- S2: serial combine across chunks ----------------
__global__ __launch_bounds__(256) void scan2_kernel(
    const float* __restrict__ cA, const float* __restrict__ cH,
    const float* __restrict__ h0, float* __restrict__ cS, float* __restrict__ finals)
{
    int idx = blockIdx.x * 256 + threadIdx.x;       // 0 .. NCH-1
    int n = idx & (Hsz - 1);
    int b = idx >> 10;

    float hp = h0[idx];
    float h;
    if (hp >= 0.0f) h = hp + 0.5f;
    else { float e = expf(hp); h = e / (1.0f + e); }

    #pragma unroll
    for (int c = 0; c < NC; c++) {
        size_t o = ((size_t)(b * NC + c) << 10) + n;
        cS[o] = h;
        h = fmaf(cA[o], h, cH[o]);
    }
    finals[idx] = h;
}

// ---------------- S3: expand chunk, residual, fp16 export ----------------
__global__ __launch_bounds__(256) void scan3_kernel(
    const float* __restrict__ GH, const float* __restrict__ inp,
    const float* __restrict__ cS, float* __restrict__ outp, __half* __restrict__ nA)
{
    int idx = blockIdx.x * 256 + threadIdx.x;       // ((b*NC + c)*Hsz) + n
    int n = idx & (Hsz - 1);
    int bc = idx >> 10;
    int c = bc & (NC - 1);
    int b = bc >> 4;

    const size_t srow = (size_t)b * Ssz + (size_t)c * CL;
    const float* gh = GH + srow * Nsz + n;
    const float* ip = inp + srow * Hsz + n;
    float* op = outp + srow * Hsz + n;
    __half* ap = nA ? nA + srow * Hsz + n : nullptr;

    float h = cS[idx];
    #pragma unroll 4
    for (int i = 0; i < CL; i++) {
        float gate = gh[(size_t)i * Nsz];
        float hid  = gh[(size_t)i * Nsz + Hsz];
        float xin  = ip[(size_t)i * Hsz];
        float a, zg;
        gates(gate, hid, a, zg);
        h = fmaf(a, h, zg);
        float o = h + xin;
        op[(size_t)i * Hsz] = o;
        if (ap) ap[(size_t)i * Hsz] = __float2half(o);
    }
}

// ---------------- launch ----------------
extern "C" void kernel_launch(void* const* d_in, const int* in_sizes, int n_in,
                              void* d_out, int out_size)
{
    const float* x  = (const float*)d_in[0];
    const float* h  = (const float*)d_in[1];
    const float* W0 = (const float*)d_in[2];
    const float* b0 = (const float*)d_in[3];
    const float* Wl = (const float*)d_in[4];
    const float* bl = (const float*)d_in[5];

    float* out_main = (float*)d_out;
    float* finals   = out_main + (size_t)Msz * Hsz;

    float *GH, *buf0, *buf1, *cA, *cH, *cS;
    __half *A16, *B16;
    cudaGetSymbolAddress((void**)&GH, g_GH);
    cudaGetSymbolAddress((void**)&buf0, g_buf0);
    cudaGetSymbolAddress((void**)&buf1, g_buf1);
    cudaGetSymbolAddress((void**)&A16, g_A16);
    cudaGetSymbolAddress((void**)&B16, g_B16);
    cudaGetSymbolAddress((void**)&cA, g_cA);
    cudaGetSymbolAddress((void**)&cH, g_cH);
    cudaGetSymbolAddress((void**)&cS, g_cS);

    cudaFuncSetAttribute(gemm_mma_kernel, cudaFuncAttributeMaxDynamicSharedMemorySize, SMEM_TOTAL);

    conv_w_kernel<<<(4 * 2097152 / 4) / 256, 256>>>(W0, Wl, B16);
    conv_x_kernel<<<((size_t)Msz * Ksz / 4) / 256, 256>>>(x, A16);

    dim3 ggrid(Msz / TM, Nsz / TN);   // (128, 16)

    for (int l = 0; l < Lsz; l++) {
        const float* inp = (l == 0) ? x : (l == 1 ? buf0 : (l == 2 ? buf1 : buf0));
        const float* bi  = (l == 0) ? b0 : bl + (size_t)(l - 1) * Nsz;
        float* outp = (l == 3) ? out_main : ((l % 2 == 0) ? buf0 : buf1);
        __half* nA = (l < 3) ? A16 : nullptr;

        gemm_mma_kernel<<<ggrid, 256, SMEM_TOTAL>>>(
            A16, B16 + (size_t)l * Nsz * Ksz, bi, GH);
        scan1_kernel<<<NTH / 256, 256>>>(GH, cA, cH);
        scan2_kernel<<<NCH / 256, 256>>>(cA, cH, h + (size_t)l * NCH,
                                         cS, finals + (size_t)l * NCH);
        scan3_kernel<<<NTH / 256, 256>>>(GH, inp, cS, outp, nA);
    }
}

// round 6
// speedup vs baseline: 10.6919x; 1.3634x over previous
#include <cuda_runtime.h>
#include <cuda_fp16.h>
#include <cstddef>
#include <cstdint>
#include <math.h>

// ---------------- problem sizes ----------------
#define Bsz 8
#define Ssz 2048
#define Hsz 1024
#define Lsz 4
#define Msz (Bsz * Ssz)   // 16384
#define Nsz (2 * Hsz)     // 2048
#define Ksz Hsz           // 1024

// ---------------- scan chunking ----------------
#define NC 64             // chunks per sequence
#define CL (Ssz / NC)     // 32 steps per chunk
#define NCH (Bsz * Hsz)   // 8192 channels
#define HC (Hsz / 2)      // 512 channel-pairs per batch
#define NTH2 ((NCH / 2) * NC)   // 262144 chunk-threads (2 channels each)

// ---------------- GEMM tile config ----------------
#define TM 128
#define TN 128
#define KC 64                 // fp16 per K-stage (128 B rows)
#define NKSTEP (Ksz / KC)     // 16
#define STAGE_BYTES 32768     // A 16K | B 16K
#define A_OFF 0
#define B_OFF 16384
#define SMEM_TOTAL (3 * STAGE_BYTES)   // 96 KB -> 2 CTAs/SM

// ---------------- scratch ----------------
__device__ __half g_GH[(size_t)Msz * Nsz];                // 64 MB (fp16 gates)
__device__ float g_buf0[(size_t)Msz * Hsz];               // 64 MB
__device__ float g_buf1[(size_t)Msz * Hsz];               // 64 MB
__device__ __half g_A16[(size_t)Msz * Ksz];               // 32 MB
__device__ __half g_B16[(size_t)Lsz * Nsz * Ksz];         // 16 MB
__device__ float g_cA[(size_t)NCH * NC];                  // 2 MB
__device__ float g_cH[(size_t)NCH * NC];                  // 2 MB
__device__ float g_cS[(size_t)NCH * NC];                  // 2 MB

// ---------------- PTX helpers (plain-sm_103-safe) ----------------
__device__ __forceinline__ uint32_t smem_u32(const void* p) {
    uint32_t a;
    asm("{ .reg .u64 t; cvta.to.shared.u64 t, %1; cvt.u32.u64 %0, t; }" : "=r"(a) : "l"(p));
    return a;
}
#define CP_ASYNC16(dst, src) \
    asm volatile("cp.async.cg.shared.global [%0], [%1], 16;" :: "r"(dst), "l"(src) : "memory")
#define CP_COMMIT() asm volatile("cp.async.commit_group;" ::: "memory")
#define CP_WAIT2()  asm volatile("cp.async.wait_group 2;" ::: "memory")
#define CP_WAIT0()  asm volatile("cp.async.wait_group 0;" ::: "memory")

__device__ __forceinline__ void ldsm4(uint32_t* r, uint32_t addr) {
    asm volatile("ldmatrix.sync.aligned.m8n8.x4.shared.b16 {%0,%1,%2,%3}, [%4];"
        : "=r"(r[0]), "=r"(r[1]), "=r"(r[2]), "=r"(r[3]) : "r"(addr));
}
__device__ __forceinline__ void mma_fp16(float* d, const uint32_t* a, uint32_t b0, uint32_t b1) {
    asm volatile("mma.sync.aligned.m16n8k16.row.col.f32.f16.f16.f32 "
                 "{%0,%1,%2,%3}, {%4,%5,%6,%7}, {%8,%9}, {%0,%1,%2,%3};"
                 : "+f"(d[0]), "+f"(d[1]), "+f"(d[2]), "+f"(d[3])
                 : "r"(a[0]), "r"(a[1]), "r"(a[2]), "r"(a[3]), "r"(b0), "r"(b1));
}

// ---------------- stage loader ----------------
__device__ __forceinline__ void load_stage(
    uint32_t sb, int m0, int n0, int k0,
    const __half* __restrict__ A16, const __half* __restrict__ B16)
{
    const int t = threadIdx.x;
    #pragma unroll
    for (int r = 0; r < 4; r++) {
        int c = t + r * 256;                 // 0..1023
        int row = c >> 3, ci = c & 7;
        uint32_t off = (uint32_t)(row << 7) + (((uint32_t)(ci << 4)) ^ ((uint32_t)(row & 7) << 4));
        size_t ga = (size_t)(m0 + row) * Ksz + k0 + ci * 8;
        size_t gb = (size_t)(n0 + row) * Ksz + k0 + ci * 8;
        CP_ASYNC16(sb + A_OFF + off, A16 + ga);
        CP_ASYNC16(sb + B_OFF + off, B16 + gb);
    }
    CP_COMMIT();
}

// ---------------- HMMA GEMM: C[M,N] = fp16(A*B^T + bias) ----------------
__global__ __launch_bounds__(256, 2)
void gemm_mma_kernel(
    const __half* __restrict__ A16, const __half* __restrict__ B16,
    const float* __restrict__ bias, __half* __restrict__ C)
{
    extern __shared__ __align__(1024) char smem[];
    const uint32_t sbase = smem_u32(smem);
    const int tid  = threadIdx.x;
    const int lane = tid & 31;
    const int w    = tid >> 5;
    const int m_warp = (w & 1) * 64;
    const int n_warp = (w >> 1) * 32;
    const int m0 = blockIdx.x * TM;
    const int n0 = blockIdx.y * TN;

    const uint32_t xv = (uint32_t)(lane & 7) << 4;
    const uint32_t a_rowbase = (uint32_t)(m_warp + (lane & 15)) << 7;
    const uint32_t a_khalf   = (uint32_t)(lane >> 4) << 4;
    const uint32_t b_rowbase = (uint32_t)(n_warp + ((lane >> 4) << 3) + (lane & 7)) << 7;
    const uint32_t b_khalf   = (uint32_t)((lane >> 3) & 1) << 4;

    float acc[4][4][4];
    #pragma unroll
    for (int i = 0; i < 4; i++)
        #pragma unroll
        for (int j = 0; j < 4; j++)
            #pragma unroll
            for (int q = 0; q < 4; q++) acc[i][j][q] = 0.0f;

    load_stage(sbase,                   m0, n0, 0,      A16, B16);
    load_stage(sbase + STAGE_BYTES,     m0, n0, KC,     A16, B16);
    load_stage(sbase + 2 * STAGE_BYTES, m0, n0, 2 * KC, A16, B16);

    #pragma unroll 1
    for (int s = 0; s < NKSTEP; s++) {
        if (s < NKSTEP - 2) { CP_WAIT2(); } else { CP_WAIT0(); }
        __syncthreads();

        const uint32_t sb = sbase + (uint32_t)(s % 3) * STAGE_BYTES;

        #pragma unroll
        for (int ks = 0; ks < 4; ks++) {
            const uint32_t kb = (uint32_t)(ks * 32);
            uint32_t ah[4][4], bh[2][4];
            #pragma unroll
            for (int i = 0; i < 4; i++) {
                uint32_t aoff = a_rowbase + ((uint32_t)(i * 16) << 7) + ((kb + a_khalf) ^ xv);
                ldsm4(ah[i], sb + A_OFF + aoff);
            }
            #pragma unroll
            for (int j = 0; j < 2; j++) {
                uint32_t boff = b_rowbase + ((uint32_t)(j * 16) << 7) + ((kb + b_khalf) ^ xv);
                ldsm4(bh[j], sb + B_OFF + boff);
            }
            #pragma unroll
            for (int i = 0; i < 4; i++) {
                #pragma unroll
                for (int jt = 0; jt < 4; jt++) {
                    const int jp = jt >> 1, jo = (jt & 1) * 2;
                    mma_fp16(acc[i][jt], ah[i], bh[jp][jo], bh[jp][jo + 1]);
                }
            }
        }

        __syncthreads();
        if (s + 3 < NKSTEP)
            load_stage(sb, m0, n0, (s + 3) * KC, A16, B16);
    }

    const int trow = lane >> 2;
    const int tcol = (lane & 3) * 2;
    #pragma unroll
    for (int i = 0; i < 4; i++) {
        #pragma unroll
        for (int jt = 0; jt < 4; jt++) {
            int row = m0 + m_warp + i * 16 + trow;
            int col = n0 + n_warp + jt * 8 + tcol;
            float2 bv = *(const float2*)&bias[col];
            *(__half2*)&C[(size_t)row * Nsz + col] =
                __floats2half2_rn(acc[i][jt][0] + bv.x, acc[i][jt][1] + bv.y);
            *(__half2*)&C[(size_t)(row + 8) * Nsz + col] =
                __floats2half2_rn(acc[i][jt][2] + bv.x, acc[i][jt][3] + bv.y);
        }
    }
}

// ---------------- fp32 -> fp16 conversions ----------------
__global__ __launch_bounds__(256) void conv_x_kernel(
    const float* __restrict__ src, __half* __restrict__ dst)
{
    size_t i = (size_t)blockIdx.x * 256 + threadIdx.x;
    float4 v = ((const float4*)src)[i];
    ((__half2*)dst)[2 * i + 0] = __floats2half2_rn(v.x, v.y);
    ((__half2*)dst)[2 * i + 1] = __floats2half2_rn(v.z, v.w);
}

__global__ __launch_bounds__(256) void conv_w_kernel(
    const float* __restrict__ W0, const float* __restrict__ Wl, __half* __restrict__ dst)
{
    size_t i = (size_t)blockIdx.x * 256 + threadIdx.x;
    size_t layer = i >> 19;
    const float* src = (layer == 0) ? W0 : (Wl + ((layer - 1) << 21));
    size_t li = i & ((1 << 19) - 1);
    float4 v = ((const float4*)src)[li];
    ((__half2*)dst)[2 * i + 0] = __floats2half2_rn(v.x, v.y);
    ((__half2*)dst)[2 * i + 1] = __floats2half2_rn(v.z, v.w);
}

// ---------------- gate math ----------------
__device__ __forceinline__ void gates(float gate, float hid, float& a, float& zg) {
    float e  = expf(-fabsf(gate));
    float sp = 1.0f / (1.0f + e);
    float z;
    if (gate >= 0.0f) { z = sp; a = e * sp; }
    else              { z = e * sp; a = sp; }
    float gv;
    if (hid >= 0.0f) gv = hid + 0.5f;
    else { float eh = expf(hid); gv = eh / (1.0f + eh); }
    zg = z * gv;
}

// ---------------- S1: per-chunk (a-product, partial state), 2 channels/thread ----------------
__global__ __launch_bounds__(256, 8) void scan1_kernel(
    const __half* __restrict__ GH, float* __restrict__ cA, float* __restrict__ cH)
{
    int idx = blockIdx.x * 256 + threadIdx.x;       // (b*NC + c)*HC + n0
    int n0 = idx & (HC - 1);
    int bc = idx >> 9;
    int c = bc & (NC - 1);
    int b = bc >> 6;

    const __half2* gh = (const __half2*)(GH + ((size_t)b * Ssz + (size_t)c * CL) * Nsz) + n0;

    float ap0 = 1.0f, hp0 = 0.0f, ap1 = 1.0f, hp1 = 0.0f;
    #pragma unroll 8
    for (int i = 0; i < CL; i++) {
        float2 g  = __half22float2(gh[(size_t)i * (Nsz / 2)]);
        float2 hd = __half22float2(gh[(size_t)i * (Nsz / 2) + HC]);
        float a0, zg0, a1, zg1;
        gates(g.x, hd.x, a0, zg0);
        gates(g.y, hd.y, a1, zg1);
        hp0 = fmaf(a0, hp0, zg0);  ap0 *= a0;
        hp1 = fmaf(a1, hp1, zg1);  ap1 *= a1;
    }
    ((float2*)cA)[idx] = make_float2(ap0, ap1);
    ((float2*)cH)[idx] = make_float2(hp0, hp1);
}

// ---------------- S2: serial combine across chunks, 2 channels/thread ----------------
__global__ __launch_bounds__(256) void scan2_kernel(
    const float* __restrict__ cA, const float* __restrict__ cH,
    const float* __restrict__ h0, float* __restrict__ cS, float* __restrict__ finals)
{
    int idx = blockIdx.x * 256 + threadIdx.x;       // b*HC + n0
    int n0 = idx & (HC - 1);
    int b = idx >> 9;

    float2 hp = ((const float2*)h0)[idx];
    float h0v, h1v;
    if (hp.x >= 0.0f) h0v = hp.x + 0.5f;
    else { float e = expf(hp.x); h0v = e / (1.0f + e); }
    if (hp.y >= 0.0f) h1v = hp.y + 0.5f;
    else { float e = expf(hp.y); h1v = e / (1.0f + e); }

    #pragma unroll
    for (int c = 0; c < NC; c++) {
        size_t o = (size_t)(b * NC + c) * HC + n0;
        ((float2*)cS)[o] = make_float2(h0v, h1v);
        float2 a = ((const float2*)cA)[o];
        float2 hh = ((const float2*)cH)[o];
        h0v = fmaf(a.x, h0v, hh.x);
        h1v = fmaf(a.y, h1v, hh.y);
    }
    ((float2*)finals)[idx] = make_float2(h0v, h1v);
}

// ---------------- S3: expand chunk, residual, fp16 export, 2 channels/thread ----------------
__global__ __launch_bounds__(256, 6) void scan3_kernel(
    const __half* __restrict__ GH, const float* __restrict__ inp,
    const float* __restrict__ cS, float* __restrict__ outp, __half* __restrict__ nA)
{
    int idx = blockIdx.x * 256 + threadIdx.x;       // (b*NC + c)*HC + n0
    int n0 = idx & (HC - 1);
    int bc = idx >> 9;
    int c = bc & (NC - 1);
    int b = bc >> 6;

    const size_t srow = (size_t)b * Ssz + (size_t)c * CL;
    const __half2* gh = (const __half2*)(GH + srow * Nsz) + n0;
    const float2* ip = (const float2*)(inp + srow * Hsz) + n0;
    float2* op = (float2*)(outp + srow * Hsz) + n0;
    __half2* ap = nA ? (__half2*)(nA + srow * Hsz) + n0 : nullptr;

    float2 hs = ((const float2*)cS)[idx];
    float h0v = hs.x, h1v = hs.y;

    #pragma unroll 4
    for (int i = 0; i < CL; i++) {
        float2 g  = __half22float2(gh[(size_t)i * (Nsz / 2)]);
        float2 hd = __half22float2(gh[(size_t)i * (Nsz / 2) + HC]);
        float2 xin = ip[(size_t)i * (Hsz / 2)];
        float a0, zg0, a1, zg1;
        gates(g.x, hd.x, a0, zg0);
        gates(g.y, hd.y, a1, zg1);
        h0v = fmaf(a0, h0v, zg0);
        h1v = fmaf(a1, h1v, zg1);
        float2 o = make_float2(h0v + xin.x, h1v + xin.y);
        op[(size_t)i * (Hsz / 2)] = o;
        if (ap) ap[(size_t)i * (Hsz / 2)] = __floats2half2_rn(o.x, o.y);
    }
}

// ---------------- launch ----------------
extern "C" void kernel_launch(void* const* d_in, const int* in_sizes, int n_in,
                              void* d_out, int out_size)
{
    const float* x  = (const float*)d_in[0];
    const float* h  = (const float*)d_in[1];
    const float* W0 = (const float*)d_in[2];
    const float* b0 = (const float*)d_in[3];
    const float* Wl = (const float*)d_in[4];
    const float* bl = (const float*)d_in[5];

    float* out_main = (float*)d_out;
    float* finals   = out_main + (size_t)Msz * Hsz;

    float *buf0, *buf1, *cA, *cH, *cS;
    __half *GH, *A16, *B16;
    cudaGetSymbolAddress((void**)&GH, g_GH);
    cudaGetSymbolAddress((void**)&buf0, g_buf0);
    cudaGetSymbolAddress((void**)&buf1, g_buf1);
    cudaGetSymbolAddress((void**)&A16, g_A16);
    cudaGetSymbolAddress((void**)&B16, g_B16);
    cudaGetSymbolAddress((void**)&cA, g_cA);
    cudaGetSymbolAddress((void**)&cH, g_cH);
    cudaGetSymbolAddress((void**)&cS, g_cS);

    cudaFuncSetAttribute(gemm_mma_kernel, cudaFuncAttributeMaxDynamicSharedMemorySize, SMEM_TOTAL);

    conv_w_kernel<<<(4 * 2097152 / 4) / 256, 256>>>(W0, Wl, B16);
    conv_x_kernel<<<((size_t)Msz * Ksz / 4) / 256, 256>>>(x, A16);

    dim3 ggrid(Msz / TM, Nsz / TN);   // (128, 16)

    for (int l = 0; l < Lsz; l++) {
        const float* inp = (l == 0) ? x : (l == 1 ? buf0 : (l == 2 ? buf1 : buf0));
        const float* bi  = (l == 0) ? b0 : bl + (size_t)(l - 1) * Nsz;
        float* outp = (l == 3) ? out_main : ((l % 2 == 0) ? buf0 : buf1);
        __half* nA = (l < 3) ? A16 : nullptr;

        gemm_mma_kernel<<<ggrid, 256, SMEM_TOTAL>>>(
            A16, B16 + (size_t)l * Nsz * Ksz, bi, GH);
        scan1_kernel<<<NTH2 / 256, 256>>>(GH, cA, cH);
        scan2_kernel<<<(NCH / 2) / 256, 256>>>(cA, cH, h + (size_t)l * NCH,
                                               cS, finals + (size_t)l * NCH);
        scan3_kernel<<<NTH2 / 256, 256>>>(GH, inp, cS, outp, nA);
    }
}